// round 5
// baseline (speedup 1.0000x reference)
#include <cuda_runtime.h>

#define N_NODES   100000
#define N_EDGES   1600000
#define D_FEAT    64
#define F4_PER_ROW (D_FEAT / 4)       // 16
#define G_BLOCKS  512
#define T_THREADS 256
#define CHUNK     196                 // ceil(100000 / 512)

// -------- scratch (static __device__; zero-initialized at load) --------
__device__ int g_deg[N_NODES];              // re-zeroed by k_aggregate each run
__device__ int g_offsets[N_NODES + 1];
__device__ int g_cursor[N_NODES];
__device__ int g_csr_src[N_EDGES];
__device__ int g_bsum[G_BLOCKS];
__device__ int g_bprefix[G_BLOCKS];
__device__ unsigned int g_bar;              // reset by k_aggregate each run

// Grid-wide barrier. Arrival: one RED.ADD. Poll: plain acquire LOAD (no RMW
// serialization at the LTS) with nanosleep backoff.
__device__ __forceinline__ void grid_barrier(unsigned int target) {
    __syncthreads();
    if (threadIdx.x == 0) {
        __threadfence();                     // release our writes
        atomicAdd(&g_bar, 1u);
        unsigned int v;
        do {
            asm volatile("ld.acquire.gpu.global.u32 %0, [%1];"
                         : "=r"(v) : "l"(&g_bar));
            if (v >= target) break;
            __nanosleep(64);
        } while (true);
    }
    __syncthreads();
}

// One persistent kernel: degree count -> exclusive scan -> CSR fill.
// Cross-phase traffic through L2 (__ldcg/__stcg/atomics).
__global__ void __launch_bounds__(T_THREADS, 4)
k_build(const int* __restrict__ edge_index, int E, int N) {
    __shared__ int sh[T_THREADS];
    __shared__ int sh_top[T_THREADS];
    const int tid  = threadIdx.x;
    const int bid  = blockIdx.x;
    const int gtid = bid * T_THREADS + tid;
    const int NT   = G_BLOCKS * T_THREADS;   // 131072

    // ---- Phase 1: degree count (RED, no return), 4x unrolled for MLP ----
    {
        int i = gtid;
        for (; i + 3 * NT < E; i += 4 * NT) {
            int d0 = __ldg(&edge_index[E + i]);
            int d1 = __ldg(&edge_index[E + i + NT]);
            int d2 = __ldg(&edge_index[E + i + 2 * NT]);
            int d3 = __ldg(&edge_index[E + i + 3 * NT]);
            atomicAdd(&g_deg[d0], 1);
            atomicAdd(&g_deg[d1], 1);
            atomicAdd(&g_deg[d2], 1);
            atomicAdd(&g_deg[d3], 1);
        }
        for (; i < E; i += NT)
            atomicAdd(&g_deg[__ldg(&edge_index[E + i])], 1);
    }
    grid_barrier(1u * G_BLOCKS);

    // ---- Phase 2a: per-block inclusive scan of its CHUNK of degrees ----
    const int base = bid * CHUNK;
    int v = 0;
    if (tid < CHUNK && base + tid < N) v = __ldcg(&g_deg[base + tid]);
    sh[tid] = v;
    __syncthreads();
    #pragma unroll
    for (int off = 1; off < T_THREADS; off <<= 1) {
        int t = (tid >= off) ? sh[tid - off] : 0;
        __syncthreads();
        sh[tid] += t;
        __syncthreads();
    }
    if (tid == T_THREADS - 1) __stcg(&g_bsum[bid], sh[tid]);
    grid_barrier(2u * G_BLOCKS);

    // ---- Phase 2b: block 0 exclusive-scans the 512 block sums ----
    if (bid == 0) {
        int a0 = __ldcg(&g_bsum[2 * tid]);
        int a1 = __ldcg(&g_bsum[2 * tid + 1]);
        int s = a0 + a1;
        sh_top[tid] = s;
        __syncthreads();
        #pragma unroll
        for (int off = 1; off < T_THREADS; off <<= 1) {
            int t = (tid >= off) ? sh_top[tid - off] : 0;
            __syncthreads();
            sh_top[tid] += t;
            __syncthreads();
        }
        int excl = sh_top[tid] - s;
        __stcg(&g_bprefix[2 * tid],     excl);
        __stcg(&g_bprefix[2 * tid + 1], excl + a0);
        if (tid == T_THREADS - 1) __stcg(&g_offsets[N], sh_top[tid]);
    }
    grid_barrier(3u * G_BLOCKS);

    // ---- Phase 2c: write offsets + cursor ----
    {
        int p = __ldcg(&g_bprefix[bid]);
        if (tid < CHUNK && base + tid < N) {
            int excl = p + sh[tid] - v;
            __stcg(&g_offsets[base + tid], excl);
            __stcg(&g_cursor[base + tid],  excl);
        }
    }
    grid_barrier(4u * G_BLOCKS);

    // ---- Phase 3: scatter srcs into CSR, 4x unrolled (hide ATOMG 318cyc) ----
    {
        int i = gtid;
        for (; i + 3 * NT < E; i += 4 * NT) {
            int s0 = __ldg(&edge_index[i]);
            int s1 = __ldg(&edge_index[i + NT]);
            int s2 = __ldg(&edge_index[i + 2 * NT]);
            int s3 = __ldg(&edge_index[i + 3 * NT]);
            int d0 = __ldg(&edge_index[E + i]);
            int d1 = __ldg(&edge_index[E + i + NT]);
            int d2 = __ldg(&edge_index[E + i + 2 * NT]);
            int d3 = __ldg(&edge_index[E + i + 3 * NT]);
            int p0 = atomicAdd(&g_cursor[d0], 1);
            int p1 = atomicAdd(&g_cursor[d1], 1);
            int p2 = atomicAdd(&g_cursor[d2], 1);
            int p3 = atomicAdd(&g_cursor[d3], 1);
            __stcg(&g_csr_src[p0], s0);
            __stcg(&g_csr_src[p1], s1);
            __stcg(&g_csr_src[p2], s2);
            __stcg(&g_csr_src[p3], s3);
        }
        for (; i < E; i += NT) {
            int s = __ldg(&edge_index[i]);
            int d = __ldg(&edge_index[E + i]);
            int pos = atomicAdd(&g_cursor[d], 1);
            __stcg(&g_csr_src[pos], s);
        }
    }
}

__device__ __forceinline__ float4 fmax4(float4 a, float4 b) {
    a.x = fmaxf(a.x, b.x); a.y = fmaxf(a.y, b.y);
    a.z = fmaxf(a.z, b.z); a.w = fmaxf(a.w, b.w);
    return a;
}

// One warp per node; half-warp per row; 4 rows per iteration via 4 LDG.128.
// Out-of-range indices clamp to end-1 (duplicate under max = no-op).
// Also resets barrier ctr + re-zeroes deg for the next replay.
__global__ void k_aggregate(const float* __restrict__ h,
                            float* __restrict__ out, int n) {
    int gtid = blockIdx.x * blockDim.x + threadIdx.x;
    if (gtid == 0) g_bar = 0;
    if (gtid < n) __stcg(&g_deg[gtid], 0);

    int warp = gtid >> 5;
    int lane = threadIdx.x & 31;
    if (warp >= n) return;

    int start = g_offsets[warp];
    int end   = g_offsets[warp + 1];
    int hw = lane >> 4;
    int fl = lane & 15;

    const float NEG_INF = __int_as_float(0xff800000);
    float4 acc = make_float4(NEG_INF, NEG_INF, NEG_INF, NEG_INF);

    const float4* __restrict__ h4 = reinterpret_cast<const float4*>(h);

    for (int base = start; base < end; base += 8) {
        int e1 = end - 1;
        int i0 = min(base +     hw, e1);
        int i1 = min(base + 2 + hw, e1);
        int i2 = min(base + 4 + hw, e1);
        int i3 = min(base + 6 + hw, e1);
        int s0 = __ldg(&g_csr_src[i0]);
        int s1 = __ldg(&g_csr_src[i1]);
        int s2 = __ldg(&g_csr_src[i2]);
        int s3 = __ldg(&g_csr_src[i3]);
        float4 v0 = __ldg(&h4[s0 * F4_PER_ROW + fl]);
        float4 v1 = __ldg(&h4[s1 * F4_PER_ROW + fl]);
        float4 v2 = __ldg(&h4[s2 * F4_PER_ROW + fl]);
        float4 v3 = __ldg(&h4[s3 * F4_PER_ROW + fl]);
        acc = fmax4(acc, fmax4(fmax4(v0, v1), fmax4(v2, v3)));
    }

    acc.x = fmaxf(acc.x, __shfl_xor_sync(0xffffffffu, acc.x, 16));
    acc.y = fmaxf(acc.y, __shfl_xor_sync(0xffffffffu, acc.y, 16));
    acc.z = fmaxf(acc.z, __shfl_xor_sync(0xffffffffu, acc.z, 16));
    acc.w = fmaxf(acc.w, __shfl_xor_sync(0xffffffffu, acc.w, 16));

    if (end == start) acc = make_float4(0.f, 0.f, 0.f, 0.f);

    if (lane < 16)
        reinterpret_cast<float4*>(out)[warp * F4_PER_ROW + fl] = acc;
}

// -------- launch: two graph nodes --------
extern "C" void kernel_launch(void* const* d_in, const int* in_sizes, int n_in,
                              void* d_out, int out_size) {
    const float* h = (const float*)d_in[0];
    const int* edge_index = (const int*)d_in[1];
    float* out = (float*)d_out;

    const int N = in_sizes[0] / D_FEAT;      // 100000
    const int E = in_sizes[1] / 2;           // 1600000

    k_build<<<G_BLOCKS, T_THREADS>>>(edge_index, E, N);

    int blocks = (N * 32 + T_THREADS - 1) / T_THREADS;   // 12500
    k_aggregate<<<blocks, T_THREADS>>>(h, out, N);
}

// round 6
// speedup vs baseline: 1.0352x; 1.0352x over previous
#include <cuda_runtime.h>

#define N_NODES   100000
#define N_EDGES   1600000
#define D_FEAT    64
#define F4_PER_ROW (D_FEAT / 4)       // 16
#define NCHAIN    2                   // chains per node (one per half-warp)

// -------- scratch (static __device__; no allocation) --------
__device__ int  g_head[NCHAIN * N_NODES];   // memset to 0xFF (=-1) each replay
__device__ int2 g_link[N_EDGES];            // (next_edge, src_node), overwritten fully

// -------- build: one pass, one atomic per edge, no scan --------
__global__ void k_build(const int* __restrict__ edge_index, int E) {
    int e = blockIdx.x * blockDim.x + threadIdx.x;
    if (e >= E) return;
    int s = __ldg(&edge_index[e]);          // src
    int d = __ldg(&edge_index[E + e]);      // dst
    int bucket = NCHAIN * d + (e & (NCHAIN - 1));
    int old = atomicExch(&g_head[bucket], e);
    g_link[e] = make_int2(old, s);          // coalesced 8B store
}

__device__ __forceinline__ float4 fmax4(float4 a, float4 b) {
    a.x = fmaxf(a.x, b.x); a.y = fmaxf(a.y, b.y);
    a.z = fmaxf(a.z, b.z); a.w = fmaxf(a.w, b.w);
    return a;
}

// One warp per node. Half-warp hw chases chain hw; lanes' fl = float4 chunk
// of the 256B feature row. Link load is uniform within the half-warp
// (broadcast), row load is one LDG.128 per lane. Combine via shfl.xor(16).
__global__ void k_aggregate(const float* __restrict__ h,
                            float* __restrict__ out, int n) {
    int gtid = blockIdx.x * blockDim.x + threadIdx.x;
    int warp = gtid >> 5;
    int lane = threadIdx.x & 31;
    if (warp >= n) return;

    int hw = lane >> 4;
    int fl = lane & 15;

    int e = __ldg(&g_head[NCHAIN * warp + hw]);
    bool isolated = (__ldg(&g_head[NCHAIN * warp]) < 0) &&
                    (__ldg(&g_head[NCHAIN * warp + 1]) < 0);

    const float NEG_INF = __int_as_float(0xff800000);
    float4 acc = make_float4(NEG_INF, NEG_INF, NEG_INF, NEG_INF);

    const float4* __restrict__ h4 = reinterpret_cast<const float4*>(h);

    while (e >= 0) {
        int2 link = __ldg(&g_link[e]);                      // (next, src)
        float4 v = __ldg(&h4[link.y * F4_PER_ROW + fl]);
        acc = fmax4(acc, v);
        e = link.x;
    }

    // combine the two half-warps (same feature chunk lives at lane and lane^16)
    acc.x = fmaxf(acc.x, __shfl_xor_sync(0xffffffffu, acc.x, 16));
    acc.y = fmaxf(acc.y, __shfl_xor_sync(0xffffffffu, acc.y, 16));
    acc.z = fmaxf(acc.z, __shfl_xor_sync(0xffffffffu, acc.z, 16));
    acc.w = fmaxf(acc.w, __shfl_xor_sync(0xffffffffu, acc.w, 16));

    if (isolated) acc = make_float4(0.f, 0.f, 0.f, 0.f);

    if (lane < 16)
        reinterpret_cast<float4*>(out)[warp * F4_PER_ROW + fl] = acc;
}

// -------- launch: memset + 2 kernels --------
extern "C" void kernel_launch(void* const* d_in, const int* in_sizes, int n_in,
                              void* d_out, int out_size) {
    const float* h = (const float*)d_in[0];
    const int* edge_index = (const int*)d_in[1];
    float* out = (float*)d_out;

    const int N = in_sizes[0] / D_FEAT;      // 100000
    const int E = in_sizes[1] / 2;           // 1600000

    void* p_head = nullptr;
    cudaGetSymbolAddress(&p_head, g_head);
    cudaMemsetAsync(p_head, 0xFF, (size_t)NCHAIN * N * sizeof(int));

    const int T = 256;
    k_build<<<(E + T - 1) / T, T>>>(edge_index, E);

    int blocks = (N * 32 + T - 1) / T;       // 12500
    k_aggregate<<<blocks, T>>>(h, out, N);
}